// round 3
// baseline (speedup 1.0000x reference)
#include <cuda_runtime.h>
#include <cstdint>

// FLoss: mean((1 - output[i, target[i]])^2), N=16777216 rows, 2 classes.
// d_in[0] = output float32 [N,2]  (128 MB)
// d_in[1] = target int32 [N]      (64 MB)
// d_out   = single float32.
//
// HBM-bound: 192 MB streamed. Exact-divisible partition: 2048 blocks x 256
// threads x 4 unrolled steps x 8 rows = 2^24. Fully unrolled -> 24
// independent LDG.128 front-batched per thread. __ldcs streaming hints.

static constexpr int N_ELEMS = 16777216;
static constexpr int BLOCK   = 256;
static constexpr int GRID    = 2048;
static constexpr int THREADS = GRID * BLOCK;          // 524288
static constexpr int NOCT    = N_ELEMS / 8;           // 2097152 octs (8 rows each)
static constexpr int ITERS   = NOCT / THREADS;        // 4, exact

__global__ void floss_zero_kernel(float* __restrict__ out) {
    if (threadIdx.x == 0 && blockIdx.x == 0) out[0] = 0.0f;
}

__device__ __forceinline__ float oct_term(float4 o0, float4 o1, int4 t,
                                          float s) {
    float a = (t.x == 0) ? o0.x : o0.y;
    float b = (t.y == 0) ? o0.z : o0.w;
    float c = (t.z == 0) ? o1.x : o1.y;
    float d = (t.w == 0) ? o1.z : o1.w;
    float da = 1.0f - a, db = 1.0f - b, dc = 1.0f - c, dd = 1.0f - d;
    s = fmaf(da, da, s);
    s = fmaf(db, db, s);
    s = fmaf(dc, dc, s);
    s = fmaf(dd, dd, s);
    return s;
}

__global__ __launch_bounds__(BLOCK) void floss_reduce_kernel(
    const float4* __restrict__ out4,   // [N/2]
    const int4*  __restrict__ tgt4,    // [N/4]
    float* __restrict__ result)
{
    int tid = blockIdx.x * BLOCK + threadIdx.x;

    float s0 = 0.0f, s1 = 0.0f, s2 = 0.0f, s3 = 0.0f;

    #pragma unroll
    for (int j = 0; j < ITERS; j++) {
        int i = tid + j * THREADS;           // oct index, rows 8i..8i+7
        // front-batched independent streaming loads
        float4 o0 = __ldcs(&out4[4 * i + 0]);
        float4 o1 = __ldcs(&out4[4 * i + 1]);
        float4 o2 = __ldcs(&out4[4 * i + 2]);
        float4 o3 = __ldcs(&out4[4 * i + 3]);
        int4   t0 = __ldcs(&tgt4[2 * i + 0]);
        int4   t1 = __ldcs(&tgt4[2 * i + 1]);

        s0 = oct_term(o0, o1, t0, s0);
        s1 = oct_term(o2, o3, t1, s1);
    }
    float sum = (s0 + s1) + (s2 + s3);

    // warp tree reduce
    #pragma unroll
    for (int off = 16; off > 0; off >>= 1)
        sum += __shfl_down_sync(0xFFFFFFFFu, sum, off);

    __shared__ float ws[BLOCK / 32];
    int lane = threadIdx.x & 31;
    int warp = threadIdx.x >> 5;
    if (lane == 0) ws[warp] = sum;
    __syncthreads();

    if (warp == 0) {
        sum = (lane < BLOCK / 32) ? ws[lane] : 0.0f;
        #pragma unroll
        for (int off = 16; off > 0; off >>= 1)
            sum += __shfl_down_sync(0xFFFFFFFFu, sum, off);
        if (lane == 0)
            atomicAdd(result, sum * (1.0f / (float)N_ELEMS));
    }
}

extern "C" void kernel_launch(void* const* d_in, const int* in_sizes, int n_in,
                              void* d_out, int out_size)
{
    const float4* out4 = (const float4*)d_in[0];
    const int4*   tgt4 = (const int4*)d_in[1];
    float*        res  = (float*)d_out;

    floss_zero_kernel<<<1, 32>>>(res);
    floss_reduce_kernel<<<GRID, BLOCK>>>(out4, tgt4, res);
}